// round 5
// baseline (speedup 1.0000x reference)
#include <cuda_runtime.h>
#include <cstdint>

// ---------------------------------------------------------------------------
// AttentionBlock: out = X + softmax_axis1(causal(Q K^T)) / sqrt(k) @ V
// B=8, T=2048, D=1024, K_SIZE=1024. All fp32 in/out; GEMMs in tf32 mma.sync.
// ---------------------------------------------------------------------------

#define BATCH 8
#define TT    2048
#define DD    1024
#define KSZ   1024

#define BM 128
#define BN 128
#define BK 32
#define PADK 36                       // floats per smem row (32 data + 4 pad)
#define TILE_F  (128 * PADK)          // one operand tile in floats
#define STAGE_F (2 * TILE_F)          // A + B per stage
#define SMEM_BYTES (2 * STAGE_F * 4)  // two stages

// ---------------- scratch (device globals; no allocation allowed) ----------
__device__ float g_Wt[3072 * 1024];                     // [n][k] = W[k][n]
__device__ float g_biasc[3072];
__device__ float g_QKV[(size_t)16384 * 3072];           // [b*T + t][3072]
__device__ float g_logits[(size_t)BATCH * TT * TT];     // logits -> probs in place
__device__ float g_Vt[(size_t)BATCH * DD * TT];         // [b][v][t]
__device__ float g_cmax[BATCH * TT];
__device__ float g_csum[BATCH * TT];

// ---------------- small helpers --------------------------------------------
__device__ __forceinline__ void cp16(float* s, const float* g) {
    unsigned sa = (unsigned)__cvta_generic_to_shared(s);
    asm volatile("cp.async.cg.shared.global [%0], [%1], 16;" :: "r"(sa), "l"(g));
}
__device__ __forceinline__ uint32_t f2tf(float x) {
    uint32_t r;
    asm("cvt.rna.tf32.f32 %0, %1;" : "=r"(r) : "f"(x));
    return r;
}
__device__ __forceinline__ void mma1688(float* d, const uint32_t* a, const uint32_t* b) {
    asm volatile(
        "mma.sync.aligned.m16n8k8.row.col.f32.tf32.tf32.f32 "
        "{%0,%1,%2,%3},{%4,%5,%6,%7},{%8,%9},{%0,%1,%2,%3};\n"
        : "+f"(d[0]), "+f"(d[1]), "+f"(d[2]), "+f"(d[3])
        : "r"(a[0]), "r"(a[1]), "r"(a[2]), "r"(a[3]), "r"(b[0]), "r"(b[1]));
}

// ---------------- generic tf32 GEMM: C[m][n] = sum_k A[m][k]*B[n][k] --------
// A row-major [M,K] stride lda; B row-major [N,K] stride ldb (i.e. C = A B^T).
// Optional bias[n] add and residual add (Res has same ldc / batch layout as C).
// grid: (N/BN, M/BM, batches). All dims assumed multiples of tile sizes.
__global__ void __launch_bounds__(256)
gemm_tf32(const float* __restrict__ A, const float* __restrict__ B,
          float* __restrict__ C,
          const float* __restrict__ bias, const float* __restrict__ Res,
          int lda, int ldb, int ldc, int K,
          long long sAb, long long sBb, long long sCb, long long sRb)
{
    extern __shared__ float sm[];
    const int tid = threadIdx.x;
    const int bz  = blockIdx.z;
    A += (size_t)bz * sAb;
    B += (size_t)bz * sBb;
    C += (size_t)bz * sCb;
    if (Res) Res += (size_t)bz * sRb;

    const int tileM = blockIdx.y * BM;
    const int tileN = blockIdx.x * BN;

    const int wid = tid >> 5, lane = tid & 31;
    const int g = lane >> 2, t4 = lane & 3;
    const int wm = (wid >> 2) * 64;   // warp row offset (2 warp-rows)
    const int wn = (wid & 3) * 32;    // warp col offset (4 warp-cols)

    float acc[4][4][4];
    #pragma unroll
    for (int i = 0; i < 4; i++)
        #pragma unroll
        for (int j = 0; j < 4; j++)
            #pragma unroll
            for (int k = 0; k < 4; k++) acc[i][j][k] = 0.f;

    auto load_tile = [&](int stage, int kt) {
        float* sA = sm + stage * STAGE_F;
        float* sB = sA + TILE_F;
        const int kk = kt * BK;
        #pragma unroll
        for (int i = 0; i < 4; i++) {
            int c = tid + i * 256;          // 1024 16B-chunks per operand tile
            int row = c >> 3;
            int kc  = (c & 7) * 4;
            cp16(sA + row * PADK + kc, A + (size_t)(tileM + row) * lda + kk + kc);
            cp16(sB + row * PADK + kc, B + (size_t)(tileN + row) * ldb + kk + kc);
        }
    };

    const int KT = K / BK;
    load_tile(0, 0);
    asm volatile("cp.async.commit_group;");

    for (int kt = 0; kt < KT; kt++) {
        if (kt + 1 < KT) {
            load_tile((kt + 1) & 1, kt + 1);
            asm volatile("cp.async.commit_group;");
            asm volatile("cp.async.wait_group 1;");
        } else {
            asm volatile("cp.async.wait_group 0;");
        }
        __syncthreads();

        const float* sA = sm + (kt & 1) * STAGE_F;
        const float* sB = sA + TILE_F;

        #pragma unroll
        for (int ks = 0; ks < 4; ks++) {            // 4 k-steps of 8
            uint32_t af[4][4], bf[4][2];
            #pragma unroll
            for (int mt = 0; mt < 4; mt++) {
                int r = wm + mt * 16 + g;
                int c = ks * 8 + t4;
                af[mt][0] = f2tf(sA[r * PADK + c]);
                af[mt][1] = f2tf(sA[(r + 8) * PADK + c]);
                af[mt][2] = f2tf(sA[r * PADK + c + 4]);
                af[mt][3] = f2tf(sA[(r + 8) * PADK + c + 4]);
            }
            #pragma unroll
            for (int nt = 0; nt < 4; nt++) {
                int n0 = wn + nt * 8 + g;
                bf[nt][0] = f2tf(sB[n0 * PADK + ks * 8 + t4]);
                bf[nt][1] = f2tf(sB[n0 * PADK + ks * 8 + t4 + 4]);
            }
            #pragma unroll
            for (int mt = 0; mt < 4; mt++)
                #pragma unroll
                for (int nt = 0; nt < 4; nt++)
                    mma1688(acc[mt][nt], af[mt], bf[nt]);
        }
        __syncthreads();
    }

    // epilogue: d0=(r,2t4) d1=(r,2t4+1) d2=(r+8,2t4) d3=(r+8,2t4+1)
    #pragma unroll
    for (int mt = 0; mt < 4; mt++) {
        #pragma unroll
        for (int nt = 0; nt < 4; nt++) {
            int r   = tileM + wm + mt * 16 + g;
            int col = tileN + wn + nt * 8 + 2 * t4;
            float2 v0 = make_float2(acc[mt][nt][0], acc[mt][nt][1]);
            float2 v1 = make_float2(acc[mt][nt][2], acc[mt][nt][3]);
            if (bias) {
                float2 bb = *(const float2*)(bias + col);
                v0.x += bb.x; v0.y += bb.y;
                v1.x += bb.x; v1.y += bb.y;
            }
            if (Res) {
                float2 r0 = *(const float2*)(Res + (size_t)r * ldc + col);
                float2 r1 = *(const float2*)(Res + (size_t)(r + 8) * ldc + col);
                v0.x += r0.x; v0.y += r0.y;
                v1.x += r1.x; v1.y += r1.y;
            }
            *(float2*)(C + (size_t)r * ldc + col)        = v0;
            *(float2*)(C + (size_t)(r + 8) * ldc + col)  = v1;
        }
    }
}

// ---------------- transpose W (3x 1024x1024) -> Wt[3072][1024] --------------
__global__ void k_transposeW(const float* __restrict__ Wq,
                             const float* __restrict__ Wk,
                             const float* __restrict__ Wv,
                             float* __restrict__ Wt)
{
    __shared__ float s[32][33];
    const int nb = blockIdx.x * 32;   // 0..3071
    const int kb = blockIdx.y * 32;   // 0..1023
    const float* W = (nb < 1024) ? Wq : (nb < 2048 ? Wk : Wv);
    const int nl = nb & 1023;
    const int tx = threadIdx.x, ty = threadIdx.y;
    #pragma unroll
    for (int r = 0; r < 4; r++) {
        int k = kb + ty + r * 8;
        s[ty + r * 8][tx] = W[k * 1024 + nl + tx];
    }
    __syncthreads();
    #pragma unroll
    for (int r = 0; r < 4; r++) {
        int n = nb + ty + r * 8;
        Wt[(size_t)n * 1024 + kb + tx] = s[tx][ty + r * 8];
    }
}

// ---------------- bias concat ------------------------------------------------
__global__ void k_biascat(const float* __restrict__ bq, const float* __restrict__ bk,
                          const float* __restrict__ bv, float* __restrict__ o)
{
    int i = blockIdx.x * 256 + threadIdx.x;
    if (i < 3072)
        o[i] = (i < 1024) ? bq[i] : (i < 2048 ? bk[i - 1024] : bv[i - 2048]);
}

// ---------------- transpose V slice of QKV -> Vt[b][v][t] --------------------
__global__ void k_transposeV(const float* __restrict__ QKV, float* __restrict__ Vt)
{
    __shared__ float s[32][33];
    const int tb = blockIdx.x * 32;   // t
    const int vb = blockIdx.y * 32;   // v
    const int b  = blockIdx.z;
    const int tx = threadIdx.x, ty = threadIdx.y;
    #pragma unroll
    for (int r = 0; r < 4; r++) {
        int t = tb + ty + r * 8;
        s[ty + r * 8][tx] = QKV[((size_t)(b * TT + t)) * 3072 + 2048 + vb + tx];
    }
    __syncthreads();
    #pragma unroll
    for (int r = 0; r < 4; r++) {
        int v = vb + ty + r * 8;
        Vt[(size_t)b * DD * TT + (size_t)v * TT + tb + tx] = s[tx][ty + r * 8];
    }
}

// ---------------- column softmax (axis = query), causal: valid rows i >= j ---
__global__ void __launch_bounds__(256)
k_colmax(const float* __restrict__ L, float* __restrict__ cmax)
{
    int t = blockIdx.x * 256 + threadIdx.x;       // 0..16383
    int b = t >> 11, j = t & 2047;
    const float* p = L + (size_t)b * TT * TT + j;
    float m = -3.402823466e38f;
    #pragma unroll 4
    for (int i = 0; i < TT; i++) {
        float v = p[(size_t)i * TT];
        if (i >= j) m = fmaxf(m, v);
    }
    cmax[t] = m;
}

__global__ void __launch_bounds__(256)
k_colsum(const float* __restrict__ L, const float* __restrict__ cmax,
         float* __restrict__ csum)
{
    int t = blockIdx.x * 256 + threadIdx.x;
    int b = t >> 11, j = t & 2047;
    const float* p = L + (size_t)b * TT * TT + j;
    float m = cmax[t];
    float s = 0.f;
    #pragma unroll 4
    for (int i = 0; i < TT; i++) {
        float v = p[(size_t)i * TT];
        if (i >= j) s += __expf(v - m);
    }
    csum[t] = s;
}

__global__ void __launch_bounds__(256)
k_probs(float* __restrict__ L, const float* __restrict__ cmax,
        const float* __restrict__ csum)
{
    int t = blockIdx.x * 256 + threadIdx.x;
    int b = t >> 11, j = t & 2047;
    float* p = L + (size_t)b * TT * TT + j;
    float m = cmax[t];
    float inv = 1.0f / (csum[t] * 32.0f);   // post-softmax 1/sqrt(1024)
    #pragma unroll 4
    for (int i = 0; i < TT; i++) {
        float v = p[(size_t)i * TT];
        p[(size_t)i * TT] = (i >= j) ? __expf(v - m) * inv : 0.f;
    }
}

// ---------------- launch ------------------------------------------------------
extern "C" void kernel_launch(void* const* d_in, const int* in_sizes, int n_in,
                              void* d_out, int out_size)
{
    (void)in_sizes; (void)n_in; (void)out_size;
    const float* X  = (const float*)d_in[0];
    const float* Wq = (const float*)d_in[1];
    const float* bq = (const float*)d_in[2];
    const float* Wk = (const float*)d_in[3];
    const float* bk = (const float*)d_in[4];
    const float* Wv = (const float*)d_in[5];
    const float* bv = (const float*)d_in[6];
    float* out = (float*)d_out;

    float *Wt, *biasc, *QKV, *logits, *Vt, *cmax, *csum;
    cudaGetSymbolAddress((void**)&Wt,     g_Wt);
    cudaGetSymbolAddress((void**)&biasc,  g_biasc);
    cudaGetSymbolAddress((void**)&QKV,    g_QKV);
    cudaGetSymbolAddress((void**)&logits, g_logits);
    cudaGetSymbolAddress((void**)&Vt,     g_Vt);
    cudaGetSymbolAddress((void**)&cmax,   g_cmax);
    cudaGetSymbolAddress((void**)&csum,   g_csum);

    cudaFuncSetAttribute(gemm_tf32, cudaFuncAttributeMaxDynamicSharedMemorySize,
                         SMEM_BYTES);

    // 1) weight transpose + bias concat
    k_transposeW<<<dim3(96, 32), dim3(32, 8)>>>(Wq, Wk, Wv, Wt);
    k_biascat<<<12, 256>>>(bq, bk, bv, biasc);

    // 2) fused QKV projection: QKV[16384,3072] = X @ Wt^T + biasc
    gemm_tf32<<<dim3(24, 128, 1), 256, SMEM_BYTES>>>(
        X, Wt, QKV, biasc, nullptr,
        1024, 1024, 3072, 1024,
        0LL, 0LL, 0LL, 0LL);

    // 3) V transpose per batch -> Vt[b][v][t]
    k_transposeV<<<dim3(64, 32, 8), dim3(32, 8)>>>(QKV, Vt);

    // 4) logits[b] = Q[b] @ K[b]^T   (Q at col 0, K at col 1024 of QKV rows)
    gemm_tf32<<<dim3(16, 16, 8), 256, SMEM_BYTES>>>(
        QKV, QKV + 1024, logits, nullptr, nullptr,
        3072, 3072, 2048, 1024,
        (long long)TT * 3072, (long long)TT * 3072, (long long)TT * TT, 0LL);

    // 5) column softmax over query axis, causal (i >= j), /32 after softmax
    k_colmax<<<64, 256>>>(logits, cmax);
    k_colsum<<<64, 256>>>(logits, cmax, csum);
    k_probs <<<64, 256>>>(logits, cmax, csum);

    // 6) out[b] = X[b] + probs[b] @ Vt[b]^T
    gemm_tf32<<<dim3(8, 16, 8), 256, SMEM_BYTES>>>(
        logits, Vt, out, nullptr, X,
        2048, 2048, 1024, 2048,
        (long long)TT * TT, (long long)DD * TT, (long long)TT * DD,
        (long long)TT * DD);
}

// round 6
// speedup vs baseline: 1.3122x; 1.3122x over previous
#include <cuda_runtime.h>
#include <cuda_bf16.h>
#include <cstdint>

// ---------------------------------------------------------------------------
// AttentionBlock: out = X + softmax_axis1(causal(Q K^T)) / sqrt(k) @ V
// B=8, T=2048, D=1024. GEMMs in bf16 mma.sync.m16n8k16 (fp32 accumulate),
// softmax/logits kept in fp32.
// ---------------------------------------------------------------------------

#define BATCH 8
#define TT    2048
#define DD    1024

#define BM 128
#define BN 128
#define BKH 64                          // k elements (bf16) per stage
#define PADH 72                         // halves per smem row (64 + 8 pad)
#define TILE_H  (128 * PADH)            // one operand tile in halves
#define STAGE_H (2 * TILE_H)            // A + B per stage
#define SMEM_BYTES (2 * STAGE_H * 2)    // two stages, bytes (73728)

// ---------------- scratch (device globals; no allocation allowed) ----------
__device__ __nv_bfloat16 g_Xb[(size_t)16384 * 1024];
__device__ __nv_bfloat16 g_Wt[(size_t)3072 * 1024];      // [n][k] = W[k][n]
__device__ float         g_biasc[3072];
__device__ __nv_bfloat16 g_QKV[(size_t)16384 * 3072];    // [b*T + t][3072]
__device__ float         g_logits[(size_t)BATCH * TT * TT];
__device__ __nv_bfloat16 g_probs[(size_t)BATCH * TT * TT];
__device__ __nv_bfloat16 g_Vt[(size_t)BATCH * DD * TT];  // [b][v][t]
__device__ float         g_cmax[BATCH * TT];
__device__ float         g_csum[BATCH * TT];

// ---------------- helpers ----------------------------------------------------
__device__ __forceinline__ void cp16(void* s, const void* g) {
    unsigned sa = (unsigned)__cvta_generic_to_shared(s);
    asm volatile("cp.async.cg.shared.global [%0], [%1], 16;" :: "r"(sa), "l"(g));
}
__device__ __forceinline__ void ldsm_x4(uint32_t* r, uint32_t saddr) {
    asm volatile("ldmatrix.sync.aligned.m8n8.x4.shared.b16 {%0,%1,%2,%3}, [%4];"
        : "=r"(r[0]), "=r"(r[1]), "=r"(r[2]), "=r"(r[3]) : "r"(saddr));
}
__device__ __forceinline__ void mma16816(float* d, const uint32_t* a,
                                         uint32_t b0, uint32_t b1) {
    asm volatile(
        "mma.sync.aligned.m16n8k16.row.col.f32.bf16.bf16.f32 "
        "{%0,%1,%2,%3},{%4,%5,%6,%7},{%8,%9},{%0,%1,%2,%3};\n"
        : "+f"(d[0]), "+f"(d[1]), "+f"(d[2]), "+f"(d[3])
        : "r"(a[0]), "r"(a[1]), "r"(a[2]), "r"(a[3]), "r"(b0), "r"(b1));
}

// ---------------- bf16 GEMM: C[m][n] = sum_k A[m][k]*B[n][k] ------------------
// A [M,K] bf16 row-major stride lda; B [N,K] bf16 row-major stride ldb.
// MODE 0: out bf16, += bias[n].  MODE 1: out fp32.  MODE 2: out fp32, += Res.
template<int MODE>
__global__ void __launch_bounds__(256)
gemm_bf16(const __nv_bfloat16* __restrict__ A, const __nv_bfloat16* __restrict__ B,
          void* __restrict__ Cv,
          const float* __restrict__ bias, const float* __restrict__ Res,
          int lda, int ldb, int ldc, int K,
          long long sAb, long long sBb, long long sCb, long long sRb)
{
    extern __shared__ __nv_bfloat16 sm[];
    const int tid = threadIdx.x;
    const int bz  = blockIdx.z;
    A += (size_t)bz * sAb;
    B += (size_t)bz * sBb;
    if (Res) Res += (size_t)bz * sRb;

    const int tileM = blockIdx.y * BM;
    const int tileN = blockIdx.x * BN;

    const int wid = tid >> 5, lane = tid & 31;
    const int g = lane >> 2, t4 = lane & 3;
    const int wm = (wid >> 2) * 64;   // 2 warp-rows of 64
    const int wn = (wid & 3) * 32;    // 4 warp-cols of 32

    // ldmatrix lane decomposition
    const int lj = lane >> 3, lr = lane & 7;
    const int mrow = (lj & 1) * 8 + lr;     // row-within-16 tile
    const int kblk = (lj >> 1) * 8;         // k-within-16 offset

    float acc[4][4][4];
    #pragma unroll
    for (int i = 0; i < 4; i++)
        #pragma unroll
        for (int j = 0; j < 4; j++)
            #pragma unroll
            for (int k = 0; k < 4; k++) acc[i][j][k] = 0.f;

    auto load_tile = [&](int stage, int kt) {
        __nv_bfloat16* sA = sm + stage * STAGE_H;
        __nv_bfloat16* sB = sA + TILE_H;
        const int kk = kt * BKH;
        #pragma unroll
        for (int i = 0; i < 4; i++) {
            int c = tid + i * 256;          // 1024 16B-chunks per operand
            int row = c >> 3;
            int kc  = (c & 7) * 8;          // halves
            cp16(sA + row * PADH + kc, A + (size_t)(tileM + row) * lda + kk + kc);
            cp16(sB + row * PADH + kc, B + (size_t)(tileN + row) * ldb + kk + kc);
        }
    };

    const uint32_t smem_u = (uint32_t)__cvta_generic_to_shared(sm);

    const int KT = K / BKH;
    load_tile(0, 0);
    asm volatile("cp.async.commit_group;");

    for (int kt = 0; kt < KT; kt++) {
        if (kt + 1 < KT) {
            load_tile((kt + 1) & 1, kt + 1);
            asm volatile("cp.async.commit_group;");
            asm volatile("cp.async.wait_group 1;");
        } else {
            asm volatile("cp.async.wait_group 0;");
        }
        __syncthreads();

        const uint32_t sA_u = smem_u + (kt & 1) * STAGE_H * 2;
        const uint32_t sB_u = sA_u + TILE_H * 2;

        #pragma unroll
        for (int ks = 0; ks < 4; ks++) {            // 4 k-steps of 16
            const int kc = ks * 16 + kblk;          // halves
            uint32_t af[4][4];
            #pragma unroll
            for (int mt = 0; mt < 4; mt++) {
                int r = wm + mt * 16 + mrow;
                ldsm_x4(af[mt], sA_u + (uint32_t)(r * PADH + kc) * 2);
            }
            uint32_t q[2][4];
            #pragma unroll
            for (int np = 0; np < 2; np++) {
                int n0 = wn + np * 16 + mrow;
                ldsm_x4(q[np], sB_u + (uint32_t)(n0 * PADH + kc) * 2);
            }
            #pragma unroll
            for (int mt = 0; mt < 4; mt++)
                #pragma unroll
                for (int nt = 0; nt < 4; nt++) {
                    int np = nt >> 1, h = nt & 1;
                    mma16816(acc[mt][nt], af[mt], q[np][h], q[np][h + 2]);
                }
        }
        __syncthreads();
    }

    // epilogue: d0=(r,2t4) d1=(r,2t4+1) d2=(r+8,2t4) d3=(r+8,2t4+1)
    #pragma unroll
    for (int mt = 0; mt < 4; mt++) {
        #pragma unroll
        for (int nt = 0; nt < 4; nt++) {
            int r   = tileM + wm + mt * 16 + g;
            int col = tileN + wn + nt * 8 + 2 * t4;
            float2 v0 = make_float2(acc[mt][nt][0], acc[mt][nt][1]);
            float2 v1 = make_float2(acc[mt][nt][2], acc[mt][nt][3]);
            if (MODE == 0) {
                float2 bb = *(const float2*)(bias + col);
                v0.x += bb.x; v0.y += bb.y;
                v1.x += bb.x; v1.y += bb.y;
                __nv_bfloat16* C = (__nv_bfloat16*)Cv + (size_t)bz * sCb;
                *(__nv_bfloat162*)(C + (size_t)r * ldc + col) =
                    __float22bfloat162_rn(v0);
                *(__nv_bfloat162*)(C + (size_t)(r + 8) * ldc + col) =
                    __float22bfloat162_rn(v1);
            } else {
                float* C = (float*)Cv + (size_t)bz * sCb;
                if (MODE == 2) {
                    float2 r0 = *(const float2*)(Res + (size_t)r * ldc + col);
                    float2 r1 = *(const float2*)(Res + (size_t)(r + 8) * ldc + col);
                    v0.x += r0.x; v0.y += r0.y;
                    v1.x += r1.x; v1.y += r1.y;
                }
                *(float2*)(C + (size_t)r * ldc + col)       = v0;
                *(float2*)(C + (size_t)(r + 8) * ldc + col) = v1;
            }
        }
    }
}

// ---------------- transpose W (3x 1024x1024 fp32) -> Wt[3072][1024] bf16 -----
__global__ void k_transposeW(const float* __restrict__ Wq,
                             const float* __restrict__ Wk,
                             const float* __restrict__ Wv,
                             __nv_bfloat16* __restrict__ Wt)
{
    __shared__ float s[32][33];
    const int nb = blockIdx.x * 32;
    const int kb = blockIdx.y * 32;
    const float* W = (nb < 1024) ? Wq : (nb < 2048 ? Wk : Wv);
    const int nl = nb & 1023;
    const int tx = threadIdx.x, ty = threadIdx.y;
    #pragma unroll
    for (int r = 0; r < 4; r++) {
        int k = kb + ty + r * 8;
        s[ty + r * 8][tx] = W[k * 1024 + nl + tx];
    }
    __syncthreads();
    #pragma unroll
    for (int r = 0; r < 4; r++) {
        int n = nb + ty + r * 8;
        Wt[(size_t)n * 1024 + kb + tx] = __float2bfloat16(s[tx][ty + r * 8]);
    }
}

// ---------------- bias concat -------------------------------------------------
__global__ void k_biascat(const float* __restrict__ bq, const float* __restrict__ bk,
                          const float* __restrict__ bv, float* __restrict__ o)
{
    int i = blockIdx.x * 256 + threadIdx.x;
    if (i < 3072)
        o[i] = (i < 1024) ? bq[i] : (i < 2048 ? bk[i - 1024] : bv[i - 2048]);
}

// ---------------- X fp32 -> bf16 ----------------------------------------------
__global__ void k_cvtX(const float2* __restrict__ in, __nv_bfloat162* __restrict__ o)
{
    int i = blockIdx.x * 256 + threadIdx.x;   // 8388608 pairs
    o[i] = __float22bfloat162_rn(in[i]);
}

// ---------------- transpose V slice of QKV -> Vt[b][v][t] (bf16) --------------
__global__ void k_transposeV(const __nv_bfloat16* __restrict__ QKV,
                             __nv_bfloat16* __restrict__ Vt)
{
    __shared__ __nv_bfloat16 s[32][34];
    const int tb = blockIdx.x * 32;   // t
    const int vb = blockIdx.y * 32;   // v
    const int b  = blockIdx.z;
    const int tx = threadIdx.x, ty = threadIdx.y;
    #pragma unroll
    for (int r = 0; r < 4; r++) {
        int t = tb + ty + r * 8;
        s[ty + r * 8][tx] = QKV[((size_t)(b * TT + t)) * 3072 + 2048 + vb + tx];
    }
    __syncthreads();
    #pragma unroll
    for (int r = 0; r < 4; r++) {
        int v = vb + ty + r * 8;
        Vt[(size_t)b * DD * TT + (size_t)v * TT + tb + tx] = s[tx][ty + r * 8];
    }
}

// ---------------- column softmax (axis = query), causal: valid rows i >= j ----
__global__ void __launch_bounds__(256)
k_colmax(const float* __restrict__ L, float* __restrict__ cmax)
{
    int t = blockIdx.x * 256 + threadIdx.x;
    int b = t >> 11, j = t & 2047;
    const float* p = L + (size_t)b * TT * TT + j;
    float m = -3.402823466e38f;
    #pragma unroll 4
    for (int i = 0; i < TT; i++) {
        float v = p[(size_t)i * TT];
        if (i >= j) m = fmaxf(m, v);
    }
    cmax[t] = m;
}

__global__ void __launch_bounds__(256)
k_colsum(const float* __restrict__ L, const float* __restrict__ cmax,
         float* __restrict__ csum)
{
    int t = blockIdx.x * 256 + threadIdx.x;
    int b = t >> 11, j = t & 2047;
    const float* p = L + (size_t)b * TT * TT + j;
    float m = cmax[t];
    float s = 0.f;
    #pragma unroll 4
    for (int i = 0; i < TT; i++) {
        float v = p[(size_t)i * TT];
        if (i >= j) s += __expf(v - m);
    }
    csum[t] = s;
}

__global__ void __launch_bounds__(256)
k_probs(const float* __restrict__ L, const float* __restrict__ cmax,
        const float* __restrict__ csum, __nv_bfloat16* __restrict__ P)
{
    int t = blockIdx.x * 256 + threadIdx.x;
    int b = t >> 11, j = t & 2047;
    const float* p = L + (size_t)b * TT * TT + j;
    __nv_bfloat16* q = P + (size_t)b * TT * TT + j;
    float m = cmax[t];
    float inv = 1.0f / (csum[t] * 32.0f);   // post-softmax 1/sqrt(1024)
    #pragma unroll 4
    for (int i = 0; i < TT; i++) {
        float v = p[(size_t)i * TT];
        q[(size_t)i * TT] =
            __float2bfloat16((i >= j) ? __expf(v - m) * inv : 0.f);
    }
}

// ---------------- launch --------------------------------------------------------
extern "C" void kernel_launch(void* const* d_in, const int* in_sizes, int n_in,
                              void* d_out, int out_size)
{
    (void)in_sizes; (void)n_in; (void)out_size;
    const float* X  = (const float*)d_in[0];
    const float* Wq = (const float*)d_in[1];
    const float* bq = (const float*)d_in[2];
    const float* Wk = (const float*)d_in[3];
    const float* bk = (const float*)d_in[4];
    const float* Wv = (const float*)d_in[5];
    const float* bv = (const float*)d_in[6];
    float* out = (float*)d_out;

    __nv_bfloat16 *Xb, *Wt, *QKV, *probs, *Vt;
    float *biasc, *logits, *cmax, *csum;
    cudaGetSymbolAddress((void**)&Xb,     g_Xb);
    cudaGetSymbolAddress((void**)&Wt,     g_Wt);
    cudaGetSymbolAddress((void**)&biasc,  g_biasc);
    cudaGetSymbolAddress((void**)&QKV,    g_QKV);
    cudaGetSymbolAddress((void**)&logits, g_logits);
    cudaGetSymbolAddress((void**)&probs,  g_probs);
    cudaGetSymbolAddress((void**)&Vt,     g_Vt);
    cudaGetSymbolAddress((void**)&cmax,   g_cmax);
    cudaGetSymbolAddress((void**)&csum,   g_csum);

    cudaFuncSetAttribute(gemm_bf16<0>, cudaFuncAttributeMaxDynamicSharedMemorySize,
                         SMEM_BYTES);
    cudaFuncSetAttribute(gemm_bf16<1>, cudaFuncAttributeMaxDynamicSharedMemorySize,
                         SMEM_BYTES);
    cudaFuncSetAttribute(gemm_bf16<2>, cudaFuncAttributeMaxDynamicSharedMemorySize,
                         SMEM_BYTES);

    // 1) weight transpose (fp32->bf16) + bias concat + X convert
    k_transposeW<<<dim3(96, 32), dim3(32, 8)>>>(Wq, Wk, Wv, Wt);
    k_biascat<<<12, 256>>>(bq, bk, bv, biasc);
    k_cvtX<<<32768, 256>>>((const float2*)X, (__nv_bfloat162*)Xb);

    // 2) fused QKV projection: QKV[16384,3072] = Xb @ Wt^T + biasc  (bf16 out)
    gemm_bf16<0><<<dim3(24, 128, 1), 256, SMEM_BYTES>>>(
        Xb, Wt, QKV, biasc, nullptr,
        1024, 1024, 3072, 1024,
        0LL, 0LL, 0LL, 0LL);

    // 3) V transpose per batch -> Vt[b][v][t]
    k_transposeV<<<dim3(64, 32, 8), dim3(32, 8)>>>(QKV, Vt);

    // 4) logits[b] = Q[b] @ K[b]^T  (fp32 out)
    gemm_bf16<1><<<dim3(16, 16, 8), 256, SMEM_BYTES>>>(
        QKV, QKV + 1024, logits, nullptr, nullptr,
        3072, 3072, 2048, 1024,
        (long long)TT * 3072, (long long)TT * 3072, (long long)TT * TT, 0LL);

    // 5) column softmax over query axis, causal (i >= j), /32 after softmax
    k_colmax<<<64, 256>>>(logits, cmax);
    k_colsum<<<64, 256>>>(logits, cmax, csum);
    k_probs <<<64, 256>>>(logits, cmax, csum, probs);

    // 6) out[b] = X[b] + probs[b] @ Vt[b]^T  (fp32 out + residual)
    gemm_bf16<2><<<dim3(8, 16, 8), 256, SMEM_BYTES>>>(
        probs, Vt, out, nullptr, X,
        2048, 2048, 1024, 2048,
        (long long)TT * TT, (long long)DD * TT, (long long)TT * DD,
        (long long)TT * DD);
}

// round 8
// speedup vs baseline: 3.1684x; 2.4146x over previous
#include <cuda_runtime.h>
#include <cuda_bf16.h>
#include <cstdint>

// ---------------------------------------------------------------------------
// AttentionBlock: out = X + softmax_axis1(causal(Q K^T))/sqrt(k) @ V
// B=8, T=2048, D=1024. bf16 mma.sync GEMMs; softmax fused into GEMM2 epilogue
// (unnormalized exp + column-sum atomics), normalization folded into V.
// ---------------------------------------------------------------------------

#define BATCH 8
#define TT    2048
#define DD    1024

#define BM 128
#define BN 128
#define BKH 64                          // k elements (bf16) per stage
#define PADH 72                         // halves per smem row (64 + 8 pad)
#define TILE_H  (128 * PADH)            // one operand tile in halves
#define STAGE_H (2 * TILE_H)            // A + B per stage
#define NST 3
#define SMEM_BYTES (NST * STAGE_H * 2)  // 110592

// ---------------- scratch (device globals; no allocation allowed) ----------
__device__ __nv_bfloat16 g_Xb[(size_t)16384 * 1024];
__device__ __nv_bfloat16 g_Wt[(size_t)3072 * 1024];      // [n][k] = W[k][n]
__device__ float         g_biasc[3072];
__device__ __nv_bfloat16 g_QKV[(size_t)16384 * 3072];    // [b*T + t][3072]
__device__ __nv_bfloat16 g_probs[(size_t)BATCH * TT * TT]; // p~ = exp(logit)
__device__ __nv_bfloat16 g_Vt[(size_t)BATCH * DD * TT];  // [b][v][t]
__device__ float         g_psum[BATCH * TT];             // column sums of exp
__device__ float         g_inv[BATCH * TT];              // 1/(32*psum)

// ---------------- helpers ----------------------------------------------------
__device__ __forceinline__ void cp16(void* s, const void* g) {
    unsigned sa = (unsigned)__cvta_generic_to_shared(s);
    asm volatile("cp.async.cg.shared.global [%0], [%1], 16;" :: "r"(sa), "l"(g));
}
__device__ __forceinline__ void ldsm_x4(uint32_t* r, uint32_t saddr) {
    asm volatile("ldmatrix.sync.aligned.m8n8.x4.shared.b16 {%0,%1,%2,%3}, [%4];"
        : "=r"(r[0]), "=r"(r[1]), "=r"(r[2]), "=r"(r[3]) : "r"(saddr));
}
__device__ __forceinline__ void mma16816(float* d, const uint32_t* a,
                                         uint32_t b0, uint32_t b1) {
    asm volatile(
        "mma.sync.aligned.m16n8k16.row.col.f32.bf16.bf16.f32 "
        "{%0,%1,%2,%3},{%4,%5,%6,%7},{%8,%9},{%0,%1,%2,%3};\n"
        : "+f"(d[0]), "+f"(d[1]), "+f"(d[2]), "+f"(d[3])
        : "r"(a[0]), "r"(a[1]), "r"(a[2]), "r"(a[3]), "r"(b0), "r"(b1));
}

// ---------------- bf16 GEMM: C[m][n] = sum_k A[m][k]*B[n][k] ------------------
// MODE 0: out bf16, += bias[n]                          (QKV projection)
// MODE 1: out bf16 = causal(exp(acc)); atomicAdd column sums to psum  (logits)
//         tiles strictly above the diagonal write zeros and exit.
// MODE 2: out fp32, += Res; k-loop truncated at tileM+BM (causal A)   (AV)
template<int MODE>
__global__ void __launch_bounds__(256)
gemm_bf16(const __nv_bfloat16* __restrict__ A, const __nv_bfloat16* __restrict__ B,
          void* __restrict__ Cv,
          const float* __restrict__ bias, const float* __restrict__ Res,
          float* __restrict__ psum,
          int lda, int ldb, int ldc, int K,
          long long sAb, long long sBb, long long sCb, long long sRb)
{
    extern __shared__ __nv_bfloat16 sm[];
    const int tid = threadIdx.x;
    const int bz  = blockIdx.z;
    A += (size_t)bz * sAb;
    B += (size_t)bz * sBb;
    if (MODE == 2) Res += (size_t)bz * sRb;

    const int tileM = blockIdx.y * BM;
    const int tileN = blockIdx.x * BN;

    // MODE 1: fully-masked tile (all j > i) -> write zeros, done.
    if (MODE == 1 && tileN >= tileM + BM) {
        __nv_bfloat16* C = (__nv_bfloat16*)Cv + (size_t)bz * sCb;
        const uint4 z = make_uint4(0, 0, 0, 0);
        #pragma unroll
        for (int i = 0; i < 8; i++) {
            int c = tid + i * 256;            // 2048 chunks of 8 bf16
            int row = c >> 4, cc = (c & 15) * 8;
            *(uint4*)(C + (size_t)(tileM + row) * ldc + tileN + cc) = z;
        }
        return;
    }

    const int wid = tid >> 5, lane = tid & 31;
    const int g = lane >> 2, t4 = lane & 3;
    const int wm = (wid >> 2) * 64;
    const int wn = (wid & 3) * 32;

    const int lj = lane >> 3, lr = lane & 7;
    const int mrow = (lj & 1) * 8 + lr;
    const int kblk = (lj >> 1) * 8;

    float acc[4][4][4];
    #pragma unroll
    for (int i = 0; i < 4; i++)
        #pragma unroll
        for (int j = 0; j < 4; j++)
            #pragma unroll
            for (int k = 0; k < 4; k++) acc[i][j][k] = 0.f;

    auto fill = [&](int s) {
        __nv_bfloat16* sA = sm + (s % NST) * STAGE_H;
        __nv_bfloat16* sB = sA + TILE_H;
        const int kk = s * BKH;
        #pragma unroll
        for (int i = 0; i < 4; i++) {
            int c = tid + i * 256;
            int row = c >> 3;
            int kc  = (c & 7) * 8;
            cp16(sA + row * PADH + kc, A + (size_t)(tileM + row) * lda + kk + kc);
            cp16(sB + row * PADH + kc, B + (size_t)(tileN + row) * ldb + kk + kc);
        }
    };

    const uint32_t smem_u = (uint32_t)__cvta_generic_to_shared(sm);
    const int Keff = (MODE == 2) ? (tileM + BM) : K;
    const int KT = Keff / BKH;            // >= 2 always

    fill(0);
    asm volatile("cp.async.commit_group;");
    fill(1);
    asm volatile("cp.async.commit_group;");

    for (int s = 0; s < KT; s++) {
        if (s < KT - 1) asm volatile("cp.async.wait_group 1;");
        else            asm volatile("cp.async.wait_group 0;");
        __syncthreads();

        if (s + 2 < KT) {
            fill(s + 2);
            asm volatile("cp.async.commit_group;");
        }

        const uint32_t sA_u = smem_u + (uint32_t)((s % NST) * STAGE_H * 2);
        const uint32_t sB_u = sA_u + TILE_H * 2;

        #pragma unroll
        for (int ks = 0; ks < 4; ks++) {
            const int kc = ks * 16 + kblk;
            uint32_t af[4][4];
            #pragma unroll
            for (int mt = 0; mt < 4; mt++) {
                int r = wm + mt * 16 + mrow;
                ldsm_x4(af[mt], sA_u + (uint32_t)(r * PADH + kc) * 2);
            }
            uint32_t q[2][4];
            #pragma unroll
            for (int np = 0; np < 2; np++) {
                int n0 = wn + np * 16 + mrow;
                ldsm_x4(q[np], sB_u + (uint32_t)(n0 * PADH + kc) * 2);
            }
            #pragma unroll
            for (int mt = 0; mt < 4; mt++)
                #pragma unroll
                for (int nt = 0; nt < 4; nt++) {
                    int np = nt >> 1, h = nt & 1;
                    mma16816(acc[mt][nt], af[mt], q[np][h], q[np][h + 2]);
                }
        }
    }

    // ---------------- epilogues ----------------
    if (MODE == 0) {
        __nv_bfloat16* C = (__nv_bfloat16*)Cv + (size_t)bz * sCb;
        #pragma unroll
        for (int mt = 0; mt < 4; mt++)
            #pragma unroll
            for (int nt = 0; nt < 4; nt++) {
                int r   = tileM + wm + mt * 16 + g;
                int col = tileN + wn + nt * 8 + 2 * t4;
                float2 bb = *(const float2*)(bias + col);
                float2 v0 = make_float2(acc[mt][nt][0] + bb.x, acc[mt][nt][1] + bb.y);
                float2 v1 = make_float2(acc[mt][nt][2] + bb.x, acc[mt][nt][3] + bb.y);
                *(__nv_bfloat162*)(C + (size_t)r * ldc + col) =
                    __float22bfloat162_rn(v0);
                *(__nv_bfloat162*)(C + (size_t)(r + 8) * ldc + col) =
                    __float22bfloat162_rn(v1);
            }
    } else if (MODE == 1) {
        __nv_bfloat16* C = (__nv_bfloat16*)Cv + (size_t)bz * sCb;
        float cs[4][2];
        #pragma unroll
        for (int nt = 0; nt < 4; nt++) { cs[nt][0] = 0.f; cs[nt][1] = 0.f; }
        #pragma unroll
        for (int mt = 0; mt < 4; mt++)
            #pragma unroll
            for (int nt = 0; nt < 4; nt++) {
                int r0 = tileM + wm + mt * 16 + g;
                int c0 = tileN + wn + nt * 8 + 2 * t4;
                float e00 = (r0     >= c0    ) ? __expf(acc[mt][nt][0]) : 0.f;
                float e01 = (r0     >= c0 + 1) ? __expf(acc[mt][nt][1]) : 0.f;
                float e10 = (r0 + 8 >= c0    ) ? __expf(acc[mt][nt][2]) : 0.f;
                float e11 = (r0 + 8 >= c0 + 1) ? __expf(acc[mt][nt][3]) : 0.f;
                *(__nv_bfloat162*)(C + (size_t)r0 * ldc + c0) =
                    __float22bfloat162_rn(make_float2(e00, e01));
                *(__nv_bfloat162*)(C + (size_t)(r0 + 8) * ldc + c0) =
                    __float22bfloat162_rn(make_float2(e10, e11));
                cs[nt][0] += e00 + e10;
                cs[nt][1] += e01 + e11;
            }
        #pragma unroll
        for (int nt = 0; nt < 4; nt++)
            #pragma unroll
            for (int h = 0; h < 2; h++) {
                float v = cs[nt][h];
                v += __shfl_xor_sync(0xffffffffu, v, 4);
                v += __shfl_xor_sync(0xffffffffu, v, 8);
                v += __shfl_xor_sync(0xffffffffu, v, 16);
                if (lane < 4)
                    atomicAdd(psum + bz * TT + tileN + wn + nt * 8 + 2 * t4 + h, v);
            }
    } else {
        float* C = (float*)Cv + (size_t)bz * sCb;
        #pragma unroll
        for (int mt = 0; mt < 4; mt++)
            #pragma unroll
            for (int nt = 0; nt < 4; nt++) {
                int r   = tileM + wm + mt * 16 + g;
                int col = tileN + wn + nt * 8 + 2 * t4;
                float2 v0 = make_float2(acc[mt][nt][0], acc[mt][nt][1]);
                float2 v1 = make_float2(acc[mt][nt][2], acc[mt][nt][3]);
                float2 r0 = *(const float2*)(Res + (size_t)r * ldc + col);
                float2 r1 = *(const float2*)(Res + (size_t)(r + 8) * ldc + col);
                v0.x += r0.x; v0.y += r0.y;
                v1.x += r1.x; v1.y += r1.y;
                *(float2*)(C + (size_t)r * ldc + col)       = v0;
                *(float2*)(C + (size_t)(r + 8) * ldc + col) = v1;
            }
    }
}

// ---------------- transpose W (3x 1024x1024 fp32) -> Wt[3072][1024] bf16 -----
__global__ void k_transposeW(const float* __restrict__ Wq,
                             const float* __restrict__ Wk,
                             const float* __restrict__ Wv,
                             __nv_bfloat16* __restrict__ Wt)
{
    __shared__ float s[32][33];
    const int nb = blockIdx.x * 32;
    const int kb = blockIdx.y * 32;
    const float* W = (nb < 1024) ? Wq : (nb < 2048 ? Wk : Wv);
    const int nl = nb & 1023;
    const int tx = threadIdx.x, ty = threadIdx.y;
    #pragma unroll
    for (int r = 0; r < 4; r++) {
        int k = kb + ty + r * 8;
        s[ty + r * 8][tx] = W[k * 1024 + nl + tx];
    }
    __syncthreads();
    #pragma unroll
    for (int r = 0; r < 4; r++) {
        int n = nb + ty + r * 8;
        Wt[(size_t)n * 1024 + kb + tx] = __float2bfloat16(s[tx][ty + r * 8]);
    }
}

// ---------------- bias concat -------------------------------------------------
__global__ void k_biascat(const float* __restrict__ bq, const float* __restrict__ bk,
                          const float* __restrict__ bv, float* __restrict__ o)
{
    int i = blockIdx.x * 256 + threadIdx.x;
    if (i < 3072)
        o[i] = (i < 1024) ? bq[i] : (i < 2048 ? bk[i - 1024] : bv[i - 2048]);
}

// ---------------- X fp32 -> bf16 (float4 vectorized) ---------------------------
__global__ void k_cvtX(const float4* __restrict__ in, __nv_bfloat162* __restrict__ o)
{
    int i = blockIdx.x * 256 + threadIdx.x;   // 4194304 float4s
    float4 v = in[i];
    o[2 * i]     = __float22bfloat162_rn(make_float2(v.x, v.y));
    o[2 * i + 1] = __float22bfloat162_rn(make_float2(v.z, v.w));
}

// ---------------- transpose V slice of QKV -> Vt[b][v][t] (bf16) --------------
__global__ void k_transposeV(const __nv_bfloat16* __restrict__ QKV,
                             __nv_bfloat16* __restrict__ Vt)
{
    __shared__ __nv_bfloat16 s[32][34];
    const int tb = blockIdx.x * 32;
    const int vb = blockIdx.y * 32;
    const int b  = blockIdx.z;
    const int tx = threadIdx.x, ty = threadIdx.y;
    #pragma unroll
    for (int r = 0; r < 4; r++) {
        int t = tb + ty + r * 8;
        s[ty + r * 8][tx] = QKV[((size_t)(b * TT + t)) * 3072 + 2048 + vb + tx];
    }
    __syncthreads();
    #pragma unroll
    for (int r = 0; r < 4; r++) {
        int v = vb + ty + r * 8;
        Vt[(size_t)b * DD * TT + (size_t)v * TT + tb + tx] = s[tx][ty + r * 8];
    }
}

// ---------------- psum zero / combine / V scale -------------------------------
__global__ void k_zero(float* __restrict__ p)
{
    p[blockIdx.x * 256 + threadIdx.x] = 0.f;
}
__global__ void k_comb(const float* __restrict__ psum, float* __restrict__ inv)
{
    int t = blockIdx.x * 256 + threadIdx.x;
    inv[t] = 1.0f / (psum[t] * 32.0f);        // post-softmax 1/sqrt(1024)
}
__global__ void k_scaleV(__nv_bfloat162* __restrict__ V2, const float* __restrict__ inv)
{
    int i = blockIdx.x * 256 + threadIdx.x;   // 8388608 bf162 pairs
    int t = (i * 2) & 2047;
    int b = i >> 20;                           // (i*2) >> 21
    __nv_bfloat162 v = V2[i];
    float iv0 = inv[b * 2048 + t];
    float iv1 = inv[b * 2048 + t + 1];
    V2[i] = __float22bfloat162_rn(make_float2(
        __bfloat162float(v.x) * iv0, __bfloat162float(v.y) * iv1));
}

// ---------------- launch --------------------------------------------------------
extern "C" void kernel_launch(void* const* d_in, const int* in_sizes, int n_in,
                              void* d_out, int out_size)
{
    (void)in_sizes; (void)n_in; (void)out_size;
    const float* X  = (const float*)d_in[0];
    const float* Wq = (const float*)d_in[1];
    const float* bq = (const float*)d_in[2];
    const float* Wk = (const float*)d_in[3];
    const float* bk = (const float*)d_in[4];
    const float* Wv = (const float*)d_in[5];
    const float* bv = (const float*)d_in[6];
    float* out = (float*)d_out;

    __nv_bfloat16 *Xb, *Wt, *QKV, *probs, *Vt;
    float *biasc, *psum, *inv;
    cudaGetSymbolAddress((void**)&Xb,    g_Xb);
    cudaGetSymbolAddress((void**)&Wt,    g_Wt);
    cudaGetSymbolAddress((void**)&biasc, g_biasc);
    cudaGetSymbolAddress((void**)&QKV,   g_QKV);
    cudaGetSymbolAddress((void**)&probs, g_probs);
    cudaGetSymbolAddress((void**)&Vt,    g_Vt);
    cudaGetSymbolAddress((void**)&psum,  g_psum);
    cudaGetSymbolAddress((void**)&inv,   g_inv);

    cudaFuncSetAttribute(gemm_bf16<0>, cudaFuncAttributeMaxDynamicSharedMemorySize,
                         SMEM_BYTES);
    cudaFuncSetAttribute(gemm_bf16<1>, cudaFuncAttributeMaxDynamicSharedMemorySize,
                         SMEM_BYTES);
    cudaFuncSetAttribute(gemm_bf16<2>, cudaFuncAttributeMaxDynamicSharedMemorySize,
                         SMEM_BYTES);

    // 1) preprocessing
    k_transposeW<<<dim3(96, 32), dim3(32, 8)>>>(Wq, Wk, Wv, Wt);
    k_biascat<<<12, 256>>>(bq, bk, bv, biasc);
    k_cvtX<<<16384, 256>>>((const float4*)X, (__nv_bfloat162*)Xb);
    k_zero<<<64, 256>>>(psum);

    // 2) QKV[16384,3072] = Xb @ Wt^T + biasc  (bf16 out)
    gemm_bf16<0><<<dim3(24, 128, 1), 256, SMEM_BYTES>>>(
        Xb, Wt, QKV, biasc, nullptr, nullptr,
        1024, 1024, 3072, 1024,
        0LL, 0LL, 0LL, 0LL);

    // 3) V transpose per batch -> Vt[b][v][t]
    k_transposeV<<<dim3(64, 32, 8), dim3(32, 8)>>>(QKV, Vt);

    // 4) p~[b] = causal(exp(Q[b] @ K[b]^T)) bf16; column sums -> psum
    gemm_bf16<1><<<dim3(16, 16, 8), 256, SMEM_BYTES>>>(
        QKV, QKV + 1024, probs, nullptr, nullptr, psum,
        3072, 3072, 2048, 1024,
        (long long)TT * 3072, (long long)TT * 3072, (long long)TT * TT, 0LL);

    // 5) inv = 1/(32*psum); scale Vt columns by inv
    k_comb<<<64, 256>>>(psum, inv);
    k_scaleV<<<32768, 256>>>((__nv_bfloat162*)Vt, inv);

    // 6) out[b] = X[b] + p~[b] @ Vt'[b]^T  (causal-truncated K loop)
    gemm_bf16<2><<<dim3(8, 16, 8), 256, SMEM_BYTES>>>(
        probs, Vt, out, nullptr, X, nullptr,
        2048, 2048, 1024, 2048,
        (long long)TT * TT, (long long)DD * TT, (long long)TT * DD,
        (long long)TT * DD);
}

// round 9
// speedup vs baseline: 3.7540x; 1.1848x over previous
#include <cuda_runtime.h>
#include <cuda_bf16.h>
#include <cstdint>

// ---------------------------------------------------------------------------
// AttentionBlock: out = X + softmax_axis1(causal(Q K^T))/sqrt(k) @ V
// B=8, T=2048, D=1024. bf16 mma.sync GEMMs (warp tile 64x64, frag double-buf,
// SW128-swizzled smem); softmax fused into GEMM2 epilogue; norm folded into V.
// ---------------------------------------------------------------------------

#define BATCH 8
#define TT    2048
#define DD    1024

#define BM 128
#define BN 128
#define BKH 64                          // bf16 k-elems per stage (128 B rows)
#define NST 3
#define TILE_B  16384                   // 128 rows x 128 bytes
#define STAGE_B (2 * TILE_B)
#define SMEM_BYTES (NST * STAGE_B)      // 98304

// ---------------- scratch (device globals; no allocation allowed) ----------
__device__ __nv_bfloat16 g_Xb[(size_t)16384 * 1024];
__device__ __nv_bfloat16 g_Wt[(size_t)3072 * 1024];        // [n][k] = W[k][n]
__device__ float         g_biasc[3072];
__device__ __nv_bfloat16 g_QKV[(size_t)16384 * 3072];      // [b*T + t][3072]
__device__ __nv_bfloat16 g_probs[(size_t)BATCH * TT * TT]; // p~ = exp(logit)
__device__ __nv_bfloat16 g_Vt[(size_t)BATCH * DD * TT];    // [b][v][t] * inv[t]
__device__ float         g_psum[BATCH * TT];
__device__ float         g_inv[BATCH * TT];

// ---------------- helpers ----------------------------------------------------
__device__ __forceinline__ void cp16(void* s, const void* g) {
    unsigned sa = (unsigned)__cvta_generic_to_shared(s);
    asm volatile("cp.async.cg.shared.global [%0], [%1], 16;" :: "r"(sa), "l"(g));
}
__device__ __forceinline__ void ldsm_x4(uint32_t* r, uint32_t saddr) {
    asm volatile("ldmatrix.sync.aligned.m8n8.x4.shared.b16 {%0,%1,%2,%3}, [%4];"
        : "=r"(r[0]), "=r"(r[1]), "=r"(r[2]), "=r"(r[3]) : "r"(saddr));
}
__device__ __forceinline__ void mma16816(float* d, const uint32_t* a,
                                         uint32_t b0, uint32_t b1) {
    asm volatile(
        "mma.sync.aligned.m16n8k16.row.col.f32.bf16.bf16.f32 "
        "{%0,%1,%2,%3},{%4,%5,%6,%7},{%8,%9},{%0,%1,%2,%3};\n"
        : "+f"(d[0]), "+f"(d[1]), "+f"(d[2]), "+f"(d[3])
        : "r"(a[0]), "r"(a[1]), "r"(a[2]), "r"(a[3]), "r"(b0), "r"(b1));
}

// ---------------- bf16 GEMM: C[m][n] = sum_k A[m][k]*B[n][k] ------------------
// CTA 128x128, 128 threads, 4 warps (2x2), warp tile 64x64.
// MODE 0: out bf16 += bias[n]                              (QKV projection)
// MODE 1: out bf16 = causal(exp(acc)); column sums -> psum (logits/probs);
//         tiles strictly above diagonal return (never read downstream).
// MODE 2: out fp32 += Res; k-loop truncated at tileM+BM    (AV, causal A)
template<int MODE>
__global__ void __launch_bounds__(128, 2)
gemm_bf16(const __nv_bfloat16* __restrict__ A, const __nv_bfloat16* __restrict__ B,
          void* __restrict__ Cv,
          const float* __restrict__ bias, const float* __restrict__ Res,
          float* __restrict__ psum,
          int lda, int ldb, int ldc, int K,
          long long sAb, long long sBb, long long sCb, long long sRb)
{
    extern __shared__ __align__(1024) char smem[];
    const int tid = threadIdx.x;
    const int bz  = blockIdx.z;
    const int tileM = blockIdx.y * BM;
    const int tileN = blockIdx.x * BN;

    if (MODE == 1 && tileN >= tileM + BM) return;   // never read by GEMM3

    A += (size_t)bz * sAb;
    B += (size_t)bz * sBb;
    if (MODE == 2) Res += (size_t)bz * sRb;

    const int wid = tid >> 5, lane = tid & 31;
    const int g = lane >> 2, t4 = lane & 3;
    const int wm = (wid >> 1) * 64;
    const int wn = (wid & 1) * 64;

    const int lj = lane >> 3, lr = lane & 7;
    const int mrow = (lj & 1) * 8 + lr;     // row within 16-row tile
    const int klo  = (lj >> 1) * 16;        // 16B-unit byte offset in k16 step
    const int swz  = lr * 16;               // xor key (row&7)<<4 == lr<<4

    float acc[4][8][4];
    #pragma unroll
    for (int i = 0; i < 4; i++)
        #pragma unroll
        for (int j = 0; j < 8; j++)
            #pragma unroll
            for (int k = 0; k < 4; k++) acc[i][j][k] = 0.f;

    const uint32_t smem_u = (uint32_t)__cvta_generic_to_shared(smem);

    auto fill = [&](int s) {
        char* base = smem + (s % NST) * STAGE_B;
        const int kk = s * BKH;
        #pragma unroll
        for (int i = 0; i < 8; i++) {                // A: 1024 chunks of 16B
            int c = tid + i * 128;
            int row = c >> 3, k16 = c & 7;
            int off = row * 128 + ((k16 * 16) ^ ((row & 7) * 16));
            cp16(base + off, A + (size_t)(tileM + row) * lda + kk + k16 * 8);
        }
        char* bb = base + TILE_B;
        #pragma unroll
        for (int i = 0; i < 8; i++) {                // B: 1024 chunks
            int c = tid + i * 128;
            int row = c >> 3, k16 = c & 7;
            int off = row * 128 + ((k16 * 16) ^ ((row & 7) * 16));
            cp16(bb + off, B + (size_t)(tileN + row) * ldb + kk + k16 * 8);
        }
    };

    auto ldf = [&](uint32_t sA_u, uint32_t sB_u, int ks,
                   uint32_t af[4], uint32_t qf0[4], uint32_t qf1[4],
                   uint32_t af1[4], uint32_t af2[4], uint32_t af3[4],
                   uint32_t qf2[4], uint32_t qf3[4]) {
        const int kb = (ks * 32 + klo) ^ swz;
        ldsm_x4(af,  sA_u + (wm + 0 * 16 + mrow) * 128 + kb);
        ldsm_x4(af1, sA_u + (wm + 1 * 16 + mrow) * 128 + kb);
        ldsm_x4(af2, sA_u + (wm + 2 * 16 + mrow) * 128 + kb);
        ldsm_x4(af3, sA_u + (wm + 3 * 16 + mrow) * 128 + kb);
        ldsm_x4(qf0, sB_u + (wn + 0 * 16 + mrow) * 128 + kb);
        ldsm_x4(qf1, sB_u + (wn + 1 * 16 + mrow) * 128 + kb);
        ldsm_x4(qf2, sB_u + (wn + 2 * 16 + mrow) * 128 + kb);
        ldsm_x4(qf3, sB_u + (wn + 3 * 16 + mrow) * 128 + kb);
    };

    const int Keff = (MODE == 2) ? (tileM + BM) : K;
    const int KT = Keff / BKH;                       // >= 2

    fill(0);
    asm volatile("cp.async.commit_group;");
    fill(1);
    asm volatile("cp.async.commit_group;");

    uint32_t af[2][4][4], qf[2][4][4];

    for (int s = 0; s < KT; s++) {
        if (s < KT - 1) asm volatile("cp.async.wait_group 1;");
        else            asm volatile("cp.async.wait_group 0;");
        __syncthreads();

        if (s + 2 < KT) {
            fill(s + 2);
            asm volatile("cp.async.commit_group;");
        }

        const uint32_t sA_u = smem_u + (uint32_t)((s % NST) * STAGE_B);
        const uint32_t sB_u = sA_u + TILE_B;

        ldf(sA_u, sB_u, 0, af[0][0], qf[0][0], qf[0][1],
            af[0][1], af[0][2], af[0][3], qf[0][2], qf[0][3]);

        #pragma unroll
        for (int ks = 0; ks < 4; ks++) {
            const int cur = ks & 1, nxt = cur ^ 1;
            if (ks < 3)
                ldf(sA_u, sB_u, ks + 1, af[nxt][0], qf[nxt][0], qf[nxt][1],
                    af[nxt][1], af[nxt][2], af[nxt][3], qf[nxt][2], qf[nxt][3]);
            #pragma unroll
            for (int mt = 0; mt < 4; mt++)
                #pragma unroll
                for (int np = 0; np < 4; np++)
                    #pragma unroll
                    for (int h = 0; h < 2; h++)
                        mma16816(acc[mt][np * 2 + h], af[cur][mt],
                                 qf[cur][np][h], qf[cur][np][h + 2]);
        }
    }

    // ---------------- epilogues ----------------
    if (MODE == 0) {
        __nv_bfloat16* C = (__nv_bfloat16*)Cv + (size_t)bz * sCb;
        #pragma unroll
        for (int mt = 0; mt < 4; mt++)
            #pragma unroll
            for (int nt = 0; nt < 8; nt++) {
                int r   = tileM + wm + mt * 16 + g;
                int col = tileN + wn + nt * 8 + 2 * t4;
                float2 bb = *(const float2*)(bias + col);
                float2 v0 = make_float2(acc[mt][nt][0] + bb.x, acc[mt][nt][1] + bb.y);
                float2 v1 = make_float2(acc[mt][nt][2] + bb.x, acc[mt][nt][3] + bb.y);
                *(__nv_bfloat162*)(C + (size_t)r * ldc + col) =
                    __float22bfloat162_rn(v0);
                *(__nv_bfloat162*)(C + (size_t)(r + 8) * ldc + col) =
                    __float22bfloat162_rn(v1);
            }
    } else if (MODE == 1) {
        __nv_bfloat16* C = (__nv_bfloat16*)Cv + (size_t)bz * sCb;
        float cs[8][2];
        #pragma unroll
        for (int nt = 0; nt < 8; nt++) { cs[nt][0] = 0.f; cs[nt][1] = 0.f; }
        #pragma unroll
        for (int mt = 0; mt < 4; mt++)
            #pragma unroll
            for (int nt = 0; nt < 8; nt++) {
                int r0 = tileM + wm + mt * 16 + g;
                int c0 = tileN + wn + nt * 8 + 2 * t4;
                float e00 = (r0     >= c0    ) ? __expf(acc[mt][nt][0]) : 0.f;
                float e01 = (r0     >= c0 + 1) ? __expf(acc[mt][nt][1]) : 0.f;
                float e10 = (r0 + 8 >= c0    ) ? __expf(acc[mt][nt][2]) : 0.f;
                float e11 = (r0 + 8 >= c0 + 1) ? __expf(acc[mt][nt][3]) : 0.f;
                *(__nv_bfloat162*)(C + (size_t)r0 * ldc + c0) =
                    __float22bfloat162_rn(make_float2(e00, e01));
                *(__nv_bfloat162*)(C + (size_t)(r0 + 8) * ldc + c0) =
                    __float22bfloat162_rn(make_float2(e10, e11));
                cs[nt][0] += e00 + e10;
                cs[nt][1] += e01 + e11;
            }
        #pragma unroll
        for (int nt = 0; nt < 8; nt++)
            #pragma unroll
            for (int h = 0; h < 2; h++) {
                float v = cs[nt][h];
                v += __shfl_xor_sync(0xffffffffu, v, 4);
                v += __shfl_xor_sync(0xffffffffu, v, 8);
                v += __shfl_xor_sync(0xffffffffu, v, 16);
                if (lane < 4)
                    atomicAdd(psum + bz * TT + tileN + wn + nt * 8 + 2 * t4 + h, v);
            }
    } else {
        float* C = (float*)Cv + (size_t)bz * sCb;
        #pragma unroll
        for (int mt = 0; mt < 4; mt++)
            #pragma unroll
            for (int nt = 0; nt < 8; nt++) {
                int r   = tileM + wm + mt * 16 + g;
                int col = tileN + wn + nt * 8 + 2 * t4;
                float2 v0 = make_float2(acc[mt][nt][0], acc[mt][nt][1]);
                float2 v1 = make_float2(acc[mt][nt][2], acc[mt][nt][3]);
                float2 r0 = *(const float2*)(Res + (size_t)r * ldc + col);
                float2 r1 = *(const float2*)(Res + (size_t)(r + 8) * ldc + col);
                v0.x += r0.x; v0.y += r0.y;
                v1.x += r1.x; v1.y += r1.y;
                *(float2*)(C + (size_t)r * ldc + col)       = v0;
                *(float2*)(C + (size_t)(r + 8) * ldc + col) = v1;
            }
    }
}

// ---------------- transpose W (3x 1024x1024 fp32) -> Wt[3072][1024] bf16 -----
__global__ void k_transposeW(const float* __restrict__ Wq,
                             const float* __restrict__ Wk,
                             const float* __restrict__ Wv,
                             __nv_bfloat16* __restrict__ Wt)
{
    __shared__ float s[32][33];
    const int nb = blockIdx.x * 32;
    const int kb = blockIdx.y * 32;
    const float* W = (nb < 1024) ? Wq : (nb < 2048 ? Wk : Wv);
    const int nl = nb & 1023;
    const int tx = threadIdx.x, ty = threadIdx.y;
    #pragma unroll
    for (int r = 0; r < 4; r++) {
        int k = kb + ty + r * 8;
        s[ty + r * 8][tx] = W[k * 1024 + nl + tx];
    }
    __syncthreads();
    #pragma unroll
    for (int r = 0; r < 4; r++) {
        int n = nb + ty + r * 8;
        Wt[(size_t)n * 1024 + kb + tx] = __float2bfloat16(s[tx][ty + r * 8]);
    }
}

// ---------------- bias concat + psum zero --------------------------------------
__global__ void k_prep(const float* __restrict__ bq, const float* __restrict__ bk,
                       const float* __restrict__ bv, float* __restrict__ biasc,
                       float* __restrict__ psum)
{
    int i = blockIdx.x * 256 + threadIdx.x;   // 16384
    psum[i] = 0.f;
    if (i < 3072)
        biasc[i] = (i < 1024) ? bq[i] : (i < 2048 ? bk[i - 1024] : bv[i - 2048]);
}

// ---------------- X fp32 -> bf16 ------------------------------------------------
__global__ void k_cvtX(const float4* __restrict__ in, __nv_bfloat162* __restrict__ o)
{
    int i = blockIdx.x * 256 + threadIdx.x;
    float4 v = in[i];
    o[2 * i]     = __float22bfloat162_rn(make_float2(v.x, v.y));
    o[2 * i + 1] = __float22bfloat162_rn(make_float2(v.z, v.w));
}

// ---------------- inv = 1/(32*psum) --------------------------------------------
__global__ void k_comb(const float* __restrict__ psum, float* __restrict__ inv)
{
    int t = blockIdx.x * 256 + threadIdx.x;
    inv[t] = 1.0f / (psum[t] * 32.0f);
}

// ---------------- transpose V slice of QKV -> Vt[b][v][t], scaled by inv[t] ----
__global__ void k_transposeVS(const __nv_bfloat16* __restrict__ QKV,
                              const float* __restrict__ inv,
                              __nv_bfloat16* __restrict__ Vt)
{
    __shared__ __nv_bfloat16 s[32][34];
    const int tb = blockIdx.x * 32;
    const int vb = blockIdx.y * 32;
    const int b  = blockIdx.z;
    const int tx = threadIdx.x, ty = threadIdx.y;
    #pragma unroll
    for (int r = 0; r < 4; r++) {
        int t = tb + ty + r * 8;
        s[ty + r * 8][tx] = QKV[((size_t)(b * TT + t)) * 3072 + 2048 + vb + tx];
    }
    __syncthreads();
    float iv = inv[b * TT + tb + tx];
    #pragma unroll
    for (int r = 0; r < 4; r++) {
        int v = vb + ty + r * 8;
        Vt[(size_t)b * DD * TT + (size_t)v * TT + tb + tx] =
            __float2bfloat16(__bfloat162float(s[tx][ty + r * 8]) * iv);
    }
}

// ---------------- launch --------------------------------------------------------
extern "C" void kernel_launch(void* const* d_in, const int* in_sizes, int n_in,
                              void* d_out, int out_size)
{
    (void)in_sizes; (void)n_in; (void)out_size;
    const float* X  = (const float*)d_in[0];
    const float* Wq = (const float*)d_in[1];
    const float* bq = (const float*)d_in[2];
    const float* Wk = (const float*)d_in[3];
    const float* bk = (const float*)d_in[4];
    const float* Wv = (const float*)d_in[5];
    const float* bv = (const float*)d_in[6];
    float* out = (float*)d_out;

    __nv_bfloat16 *Xb, *Wt, *QKV, *probs, *Vt;
    float *biasc, *psum, *inv;
    cudaGetSymbolAddress((void**)&Xb,    g_Xb);
    cudaGetSymbolAddress((void**)&Wt,    g_Wt);
    cudaGetSymbolAddress((void**)&biasc, g_biasc);
    cudaGetSymbolAddress((void**)&QKV,   g_QKV);
    cudaGetSymbolAddress((void**)&probs, g_probs);
    cudaGetSymbolAddress((void**)&Vt,    g_Vt);
    cudaGetSymbolAddress((void**)&psum,  g_psum);
    cudaGetSymbolAddress((void**)&inv,   g_inv);

    cudaFuncSetAttribute(gemm_bf16<0>, cudaFuncAttributeMaxDynamicSharedMemorySize,
                         SMEM_BYTES);
    cudaFuncSetAttribute(gemm_bf16<1>, cudaFuncAttributeMaxDynamicSharedMemorySize,
                         SMEM_BYTES);
    cudaFuncSetAttribute(gemm_bf16<2>, cudaFuncAttributeMaxDynamicSharedMemorySize,
                         SMEM_BYTES);

    // 1) preprocessing
    k_transposeW<<<dim3(96, 32), dim3(32, 8)>>>(Wq, Wk, Wv, Wt);
    k_prep<<<64, 256>>>(bq, bk, bv, biasc, psum);
    k_cvtX<<<16384, 256>>>((const float4*)X, (__nv_bfloat162*)Xb);

    // 2) QKV[16384,3072] = Xb @ Wt^T + biasc  (bf16 out)
    gemm_bf16<0><<<dim3(24, 128, 1), 128, SMEM_BYTES>>>(
        Xb, Wt, QKV, biasc, nullptr, nullptr,
        1024, 1024, 3072, 1024,
        0LL, 0LL, 0LL, 0LL);

    // 3) p~[b] = causal(exp(Q[b] @ K[b]^T)) bf16; column sums -> psum
    gemm_bf16<1><<<dim3(16, 16, 8), 128, SMEM_BYTES>>>(
        QKV, QKV + 1024, probs, nullptr, nullptr, psum,
        3072, 3072, 2048, 1024,
        (long long)TT * 3072, (long long)TT * 3072, (long long)TT * TT, 0LL);

    // 4) inv = 1/(32*psum); V transpose + scale -> Vt[b][v][t]
    k_comb<<<64, 256>>>(psum, inv);
    k_transposeVS<<<dim3(64, 32, 8), dim3(32, 8)>>>(QKV, inv, Vt);

    // 5) out[b] = X[b] + p~[b] @ Vt'[b]^T  (causal-truncated K loop)
    gemm_bf16<2><<<dim3(8, 16, 8), 128, SMEM_BYTES>>>(
        probs, Vt, out, nullptr, X, nullptr,
        2048, 2048, 1024, 2048,
        (long long)TT * TT, (long long)DD * TT, (long long)TT * DD,
        (long long)TT * DD);
}